// round 13
// baseline (speedup 1.0000x reference)
#include <cuda_runtime.h>
#include <cuda_bf16.h>

#define N_NODES 50000
#define N_EDGES 800000
#define D       64
#define ROWS    64         // rows per dense block
#define DBLOCK  256        // dense threads (each owns 2 rows x 8 cols)
#define WSTRIDE 68         // floats per k-row of sW (17 float4: 16 slots + pad)
#define XSTRIDE 36         // floats per row of sX (32 k + pad 4)
#define CAP     64         // bucket capacity per node (max degree ~35 for this input)
#define OVF_MAX 4096

// Scratch (__device__ globals; zero-initialized at module load).
// Invariants restored every call: g_cnt zeroed by gather, g_ovf_cnt by reset.
__device__ int  g_cnt[N_NODES];
__device__ int2 g_edge[N_NODES * CAP];   // bucket slots: {src, float_as_int(w)}
__device__ int  g_ovf_cnt;
__device__ int4 g_ovf[OVF_MAX];          // {dst, src, w_bits, pad} overflow spill
__device__ float g_neigh[N_NODES * D];

// ---------------------------------------------------------------------------
// K0: tiny reset (keeps dense as the 4th launch so ncu profiles it)
// ---------------------------------------------------------------------------
__global__ void reset_kernel() {
    if (threadIdx.x == 0 && blockIdx.x == 0) g_ovf_cnt = 0;
}

// ---------------------------------------------------------------------------
// K1: bucket-scatter edges (R7 configuration: 8 edges/thread, interleaved).
// ---------------------------------------------------------------------------
__device__ __forceinline__ void bucket_put(int d, int s, float w) {
    int p = atomicAdd(&g_cnt[d], 1);
    if (p < CAP) {
        g_edge[d * CAP + p] = make_int2(s, __float_as_int(w));
    } else {
        int o = atomicAdd(&g_ovf_cnt, 1);
        if (o < OVF_MAX) g_ovf[o] = make_int4(d, s, __float_as_int(w), 0);
    }
}

__global__ void bucket_kernel(const int4*   __restrict__ src4,
                              const int4*   __restrict__ dst4,
                              const float4* __restrict__ w4) {
    int t = blockIdx.x * blockDim.x + threadIdx.x;
    int base = t * 2;                       // 2 int4 groups = 8 edges
    const int NQ = N_EDGES / 4;
#pragma unroll
    for (int g = 0; g < 2; g++) {
        int q = base + g;
        if (q < NQ) {
            int4   s = src4[q];
            int4   d = dst4[q];
            float4 w = w4[q];
            bucket_put(d.x, s.x, w.x);
            bucket_put(d.y, s.y, w.y);
            bucket_put(d.z, s.z, w.z);
            bucket_put(d.w, s.w, w.w);
        }
    }
}

// ---------------------------------------------------------------------------
// K2: gather-side segment reduce over buckets (R7 configuration, MLP=8).
// One warp per node; lane l owns dims 2l, 2l+1. Resets g_cnt.
// ---------------------------------------------------------------------------
#define GW 8   // warps per gather block
__global__ __launch_bounds__(GW * 32)
void gather_kernel(const float* __restrict__ h) {
    __shared__ int2 sE[GW][32];
    int wslot = threadIdx.x >> 5;
    int warp  = (blockIdx.x * blockDim.x + threadIdx.x) >> 5;
    int lane  = threadIdx.x & 31;
    if (warp >= N_NODES) return;

    int cnt = g_cnt[warp];
    int m   = min(cnt, CAP);
    const int2* bucket = g_edge + warp * CAP;

    float2 acc = make_float2(0.f, 0.f);
    const float* hl = h + 2 * lane;

    for (int e0 = 0; e0 < m; e0 += 32) {
        int n = min(32, m - e0);
        if (lane < n) sE[wslot][lane] = bucket[e0 + lane];
        __syncwarp();
        int j = 0;
        for (; j + 8 <= n; j += 8) {
            float2 hv[8];
            float  ww[8];
#pragma unroll
            for (int q = 0; q < 8; q++) {
                int2 e = sE[wslot][j + q];
                ww[q] = __int_as_float(e.y);
                hv[q] = *reinterpret_cast<const float2*>(hl + (size_t)e.x * D);
            }
#pragma unroll
            for (int q = 0; q < 8; q++) {
                acc.x = fmaf(ww[q], hv[q].x, acc.x);
                acc.y = fmaf(ww[q], hv[q].y, acc.y);
            }
        }
        if (j < n) {
            float2 hv[7];
            float  ww[7];
            int mm = n - j;
#pragma unroll
            for (int q = 0; q < 7; q++) {
                if (q < mm) {
                    int2 e = sE[wslot][j + q];
                    ww[q] = __int_as_float(e.y);
                    hv[q] = *reinterpret_cast<const float2*>(hl + (size_t)e.x * D);
                }
            }
#pragma unroll
            for (int q = 0; q < 7; q++) {
                if (q < mm) {
                    acc.x = fmaf(ww[q], hv[q].x, acc.x);
                    acc.y = fmaf(ww[q], hv[q].y, acc.y);
                }
            }
        }
        __syncwarp();
    }

    // Overflow safety net (never taken for this input; correctness guard)
    if (cnt > CAP) {
        int oc = min(g_ovf_cnt, OVF_MAX);
        for (int i = 0; i < oc; i++) {
            int4 e = g_ovf[i];
            if (e.x == warp) {
                float ww = __int_as_float(e.z);
                float2 hv = *reinterpret_cast<const float2*>(hl + (size_t)e.y * D);
                acc.x = fmaf(ww, hv.x, acc.x);
                acc.y = fmaf(ww, hv.y, acc.y);
            }
        }
    }

    *reinterpret_cast<float2*>(g_neigh + (size_t)warp * D + 2 * lane) = acc;
    if (lane == 0) g_cnt[warp] = 0;          // restore invariant
}

// ---------------------------------------------------------------------------
// K3: dense  out = relu([h | neigh] @ [W_self | W_neigh]^T + b)
// Tile 2 rows x 8 cols per thread; ROWS=64/block, grid 782.
// sX row-major [r][k], stride 36: staging = direct STS.128 (no swizzle ALU,
// each 8-lane group covers 128B of distinct banks); x for 4 consecutive k
// = 1 LDS.128 per row. Inner loop per 4k: 10 LDS + 64 FFMA (FFMA-dominated).
// sW[k][slot] stride 68, slot-interleaved (cols 8cg..8cg+3 / 8cg+4..8cg+7
// in slots cg / cg+8): conflict-free broadcast LDS.128, coalesced fill.
// ---------------------------------------------------------------------------
__global__ __launch_bounds__(DBLOCK)
void dense_kernel(const float* __restrict__ h,
                  const float* __restrict__ Ws, const float* __restrict__ bs,
                  const float* __restrict__ Wn, const float* __restrict__ bn,
                  float* __restrict__ out) {
    __shared__ __align__(16) float sW[128 * WSTRIDE];
    __shared__ __align__(16) float sX[64 * XSTRIDE];
    __shared__ float sB[64];

    const int tid     = threadIdx.x;
    const int cg      = tid & 7;      // col group: cols [8cg, 8cg+8)
    const int rg      = tid >> 3;     // row group: rows {2rg, 2rg+1}
    const int rowBase = blockIdx.x * ROWS;

    // Fill sW: consecutive tid -> consecutive k (coalesced 128B global reads).
    for (int idx = tid; idx < 128 * 64; idx += DBLOCK) {
        int kk = idx & 63;
        int j  = (idx >> 6) & 63;
        int m  = idx >> 12;
        float v = m ? Wn[j * 64 + kk] : Ws[j * 64 + kk];
        int slot = (j >> 3) + ((j >> 2) & 1) * 8;
        sW[(m * 64 + kk) * WSTRIDE + slot * 4 + (j & 3)] = v;
    }
    if (tid < 64) sB[tid] = bs[tid] + bn[tid];

    float acc[2][8];
#pragma unroll
    for (int i = 0; i < 2; i++)
#pragma unroll
        for (int j = 0; j < 8; j++) acc[i][j] = 0.f;

    const float* x0base = sX + (rg * 2 + 0) * XSTRIDE;
    const float* x1base = sX + (rg * 2 + 1) * XSTRIDE;

    for (int kc = 0; kc < 4; kc++) {
        const float* srcp = (kc < 2) ? h : g_neigh;
        const int colBase = (kc & 1) * 32;

        __syncthreads();  // protect sX reuse (covers sW/sB on first iter)

        // Stage 64 rows x 32 k: 512 float4, 2 per thread.
        // Coalesced 512B/warp global reads -> direct STS.128 into [r][k].
#pragma unroll
        for (int p = 0; p < 2; p++) {
            int f  = tid + DBLOCK * p;       // float4 index 0..511
            int r  = f >> 3;                 // row 0..63
            int k4 = (f & 7) * 4;            // k offset 0,4,..,28
            int rr = rowBase + r;
            float4 v = make_float4(0.f, 0.f, 0.f, 0.f);
            if (rr < N_NODES)
                v = *reinterpret_cast<const float4*>(srcp + (size_t)rr * D + colBase + k4);
            *reinterpret_cast<float4*>(sX + r * XSTRIDE + k4) = v;
        }
        __syncthreads();

        const float4* wbase = reinterpret_cast<const float4*>(sW) + (kc * 32) * 17 + cg;

#pragma unroll
        for (int kg = 0; kg < 8; kg++) {
            float4 x0 = *reinterpret_cast<const float4*>(x0base + kg * 4);
            float4 x1 = *reinterpret_cast<const float4*>(x1base + kg * 4);
            float xa[4] = {x0.x, x0.y, x0.z, x0.w};
            float xb[4] = {x1.x, x1.y, x1.z, x1.w};
#pragma unroll
            for (int i = 0; i < 4; i++) {
                int kk = kg * 4 + i;
                float4 wa = wbase[kk * 17];       // cols 8cg..8cg+3
                float4 wb = wbase[kk * 17 + 8];   // cols 8cg+4..8cg+7
                float w8[8] = {wa.x, wa.y, wa.z, wa.w, wb.x, wb.y, wb.z, wb.w};
#pragma unroll
                for (int j = 0; j < 8; j++) {
                    acc[0][j] = fmaf(xa[i], w8[j], acc[0][j]);
                    acc[1][j] = fmaf(xb[i], w8[j], acc[1][j]);
                }
            }
        }
    }

    // Epilogue: bias + relu, 2x STG.128 per row
    float bj[8];
#pragma unroll
    for (int j = 0; j < 8; j++) bj[j] = sB[cg * 8 + j];

#pragma unroll
    for (int i = 0; i < 2; i++) {
        int rr = rowBase + rg * 2 + i;
        if (rr < N_NODES) {
            float4 o0, o1;
            o0.x = fmaxf(acc[i][0] + bj[0], 0.f);
            o0.y = fmaxf(acc[i][1] + bj[1], 0.f);
            o0.z = fmaxf(acc[i][2] + bj[2], 0.f);
            o0.w = fmaxf(acc[i][3] + bj[3], 0.f);
            o1.x = fmaxf(acc[i][4] + bj[4], 0.f);
            o1.y = fmaxf(acc[i][5] + bj[5], 0.f);
            o1.z = fmaxf(acc[i][6] + bj[6], 0.f);
            o1.w = fmaxf(acc[i][7] + bj[7], 0.f);
            float4* op = reinterpret_cast<float4*>(out + (size_t)rr * D + cg * 8);
            op[0] = o0;
            op[1] = o1;
        }
    }
}

// ---------------------------------------------------------------------------
// kernel_launch
//   0: h [N,D] f32   1: edge_src [E] i32   2: edge_dst [E] i32   3: edge_w [E] f32
//   4: W_self [D,D]  5: b_self [D]         6: W_neigh [D,D]      7: b_neigh [D]
// ---------------------------------------------------------------------------
extern "C" void kernel_launch(void* const* d_in, const int* in_sizes, int n_in,
                              void* d_out, int out_size) {
    const float* h        = (const float*)d_in[0];
    const int*   edge_src = (const int*)  d_in[1];
    const int*   edge_dst = (const int*)  d_in[2];
    const float* edge_w   = (const float*)d_in[3];
    const float* W_self   = (const float*)d_in[4];
    const float* b_self   = (const float*)d_in[5];
    const float* W_neigh  = (const float*)d_in[6];
    const float* b_neigh  = (const float*)d_in[7];
    float* out = (float*)d_out;

    reset_kernel<<<1, 32>>>();

    {
        // 8 edges per thread (R7 configuration)
        int threadsTotal = N_EDGES / 8;
        int blocks = (threadsTotal + 255) / 256;
        bucket_kernel<<<blocks, 256>>>((const int4*)edge_src, (const int4*)edge_dst,
                                       (const float4*)edge_w);
    }

    {
        int blocks = (N_NODES + GW - 1) / GW;
        gather_kernel<<<blocks, GW * 32>>>(h);
    }

    {
        int blocks = (N_NODES + ROWS - 1) / ROWS;
        dense_kernel<<<blocks, DBLOCK>>>(h, W_self, b_self, W_neigh, b_neigh, out);
    }
}

// round 14
// speedup vs baseline: 1.5571x; 1.5571x over previous
#include <cuda_runtime.h>
#include <cuda_bf16.h>

#define N_NODES 50000
#define N_EDGES 800000
#define D       64
#define ROWS    64         // rows per dense block
#define DBLOCK  256        // dense threads (each owns 2 rows x 8 cols)
#define WSTRIDE 68         // floats per k-row of sW (17 float4: 16 slots + pad)
#define XSTRIDE 68         // floats per k-row of sX
#define CAP     64         // bucket capacity per node (max degree ~35 for this input)
#define OVF_MAX 4096

// Scratch (__device__ globals; zero-initialized at module load).
// Invariants restored every call: g_cnt zeroed by gather, g_ovf_cnt by reset.
__device__ int  g_cnt[N_NODES];
__device__ int2 g_edge[N_NODES * CAP];   // bucket slots: {src, float_as_int(w)}
__device__ int  g_ovf_cnt;
__device__ int4 g_ovf[OVF_MAX];          // {dst, src, w_bits, pad} overflow spill
__device__ float g_neigh[N_NODES * D];

// ---------------------------------------------------------------------------
// K0: tiny reset (also used as a launch-slot shim so ncu captures gather)
// ---------------------------------------------------------------------------
__global__ void reset_kernel() {
    if (threadIdx.x == 0 && blockIdx.x == 0) g_ovf_cnt = 0;
}

// ---------------------------------------------------------------------------
// K1: bucket-scatter edges (R7 configuration: 8 edges/thread, interleaved).
// ---------------------------------------------------------------------------
__device__ __forceinline__ void bucket_put(int d, int s, float w) {
    int p = atomicAdd(&g_cnt[d], 1);
    if (p < CAP) {
        g_edge[d * CAP + p] = make_int2(s, __float_as_int(w));
    } else {
        int o = atomicAdd(&g_ovf_cnt, 1);
        if (o < OVF_MAX) g_ovf[o] = make_int4(d, s, __float_as_int(w), 0);
    }
}

__global__ void bucket_kernel(const int4*   __restrict__ src4,
                              const int4*   __restrict__ dst4,
                              const float4* __restrict__ w4) {
    int t = blockIdx.x * blockDim.x + threadIdx.x;
    int base = t * 2;                       // 2 int4 groups = 8 edges
    const int NQ = N_EDGES / 4;
#pragma unroll
    for (int g = 0; g < 2; g++) {
        int q = base + g;
        if (q < NQ) {
            int4   s = src4[q];
            int4   d = dst4[q];
            float4 w = w4[q];
            bucket_put(d.x, s.x, w.x);
            bucket_put(d.y, s.y, w.y);
            bucket_put(d.z, s.z, w.z);
            bucket_put(d.w, s.w, w.w);
        }
    }
}

// ---------------------------------------------------------------------------
// K2: gather v2 — 2 edges per warp-load.
// Lanes split 16/16: half h processes edges j+h; lane owns dims 4hl..4hl+3
// via LDG.128 (one warp load = 2 rows = 512B, fully coalesced). Batch of 8
// edges = 4 independent LDG.128/lane. Halves combined with 4 shfl_xor(16);
// lanes 0-15 write the row as one float4. Resets g_cnt (zero-invariant).
// ---------------------------------------------------------------------------
#define GW 8   // warps per gather block
__global__ __launch_bounds__(GW * 32)
void gather_kernel(const float* __restrict__ h) {
    __shared__ int2 sE[GW][32];
    int wslot = threadIdx.x >> 5;
    int warp  = (blockIdx.x * blockDim.x + threadIdx.x) >> 5;
    int lane  = threadIdx.x & 31;
    if (warp >= N_NODES) return;

    int cnt = g_cnt[warp];
    int m   = min(cnt, CAP);
    const int2* bucket = g_edge + warp * CAP;

    const int half = lane >> 4;    // 0: even-indexed edges, 1: odd
    const int hl   = lane & 15;    // dim group: dims [4hl, 4hl+4)

    float4 acc = make_float4(0.f, 0.f, 0.f, 0.f);
    const float* hq = h + 4 * hl;

    for (int e0 = 0; e0 < m; e0 += 32) {
        int n = min(32, m - e0);
        if (lane < n) sE[wslot][lane] = bucket[e0 + lane];
        __syncwarp();

        int j = 0;
        for (; j + 8 <= n; j += 8) {           // 8 edges: 4 per half
            float4 hv[4];
            float  ww[4];
#pragma unroll
            for (int q = 0; q < 4; q++) {
                int2 e = sE[wslot][j + 2 * q + half];
                ww[q] = __int_as_float(e.y);
                hv[q] = *reinterpret_cast<const float4*>(hq + (size_t)e.x * D);
            }
#pragma unroll
            for (int q = 0; q < 4; q++) {
                acc.x = fmaf(ww[q], hv[q].x, acc.x);
                acc.y = fmaf(ww[q], hv[q].y, acc.y);
                acc.z = fmaf(ww[q], hv[q].z, acc.z);
                acc.w = fmaf(ww[q], hv[q].w, acc.w);
            }
        }
        for (; j < n; j += 2) {                // tail, 2 edges per step
            int idx = j + half;
            if (idx < n) {
                int2 e = sE[wslot][idx];
                float wv = __int_as_float(e.y);
                float4 hv = *reinterpret_cast<const float4*>(hq + (size_t)e.x * D);
                acc.x = fmaf(wv, hv.x, acc.x);
                acc.y = fmaf(wv, hv.y, acc.y);
                acc.z = fmaf(wv, hv.z, acc.z);
                acc.w = fmaf(wv, hv.w, acc.w);
            }
        }
        __syncwarp();
    }

    // Overflow safety net (never taken for this input): lower half only,
    // applied pre-combine so each overflow edge is counted exactly once.
    if (cnt > CAP && half == 0) {
        int oc = min(g_ovf_cnt, OVF_MAX);
        for (int i = 0; i < oc; i++) {
            int4 e = g_ovf[i];
            if (e.x == warp) {
                float wv = __int_as_float(e.z);
                float4 hv = *reinterpret_cast<const float4*>(hq + (size_t)e.y * D);
                acc.x = fmaf(wv, hv.x, acc.x);
                acc.y = fmaf(wv, hv.y, acc.y);
                acc.z = fmaf(wv, hv.z, acc.z);
                acc.w = fmaf(wv, hv.w, acc.w);
            }
        }
    }

    // combine halves
    acc.x += __shfl_xor_sync(0xffffffffu, acc.x, 16);
    acc.y += __shfl_xor_sync(0xffffffffu, acc.y, 16);
    acc.z += __shfl_xor_sync(0xffffffffu, acc.z, 16);
    acc.w += __shfl_xor_sync(0xffffffffu, acc.w, 16);

    if (half == 0)
        *reinterpret_cast<float4*>(g_neigh + (size_t)warp * D + 4 * hl) = acc;
    if (lane == 0) g_cnt[warp] = 0;          // restore invariant
}

// ---------------------------------------------------------------------------
// K3: dense (EXACT R12 revert — measured 42.6us).
// Tile 2 rows x 8 cols per thread; ROWS=64/block, grid 782.
// sW[k][slot] stride 68, slot-interleaved; sX[k][r^swz(k)] stride 68.
// ---------------------------------------------------------------------------
__global__ __launch_bounds__(DBLOCK)
void dense_kernel(const float* __restrict__ h,
                  const float* __restrict__ Ws, const float* __restrict__ bs,
                  const float* __restrict__ Wn, const float* __restrict__ bn,
                  float* __restrict__ out) {
    __shared__ __align__(16) float sW[128 * WSTRIDE];
    __shared__ __align__(16) float sX[32 * XSTRIDE];
    __shared__ float sB[64];

    const int tid     = threadIdx.x;
    const int cg      = tid & 7;      // col group: cols [8cg, 8cg+8)
    const int rg      = tid >> 3;     // row group: rows {2rg, 2rg+1}
    const int rowBase = blockIdx.x * ROWS;

    for (int idx = tid; idx < 128 * 64; idx += DBLOCK) {
        int kk = idx & 63;
        int j  = (idx >> 6) & 63;
        int m  = idx >> 12;
        float v = m ? Wn[j * 64 + kk] : Ws[j * 64 + kk];
        int slot = (j >> 3) + ((j >> 2) & 1) * 8;
        sW[(m * 64 + kk) * WSTRIDE + slot * 4 + (j & 3)] = v;
    }
    if (tid < 64) sB[tid] = bs[tid] + bn[tid];

    float acc[2][8];
#pragma unroll
    for (int i = 0; i < 2; i++)
#pragma unroll
        for (int j = 0; j < 8; j++) acc[i][j] = 0.f;

    for (int kc = 0; kc < 4; kc++) {
        const float* srcp = (kc < 2) ? h : g_neigh;
        const int colBase = (kc & 1) * 32;

        __syncthreads();

#pragma unroll
        for (int p = 0; p < 2; p++) {
            int f  = tid + DBLOCK * p;
            int r  = f >> 3;
            int k4 = (f & 7) * 4;
            int rr = rowBase + r;
            float4 v = make_float4(0.f, 0.f, 0.f, 0.f);
            if (rr < N_NODES)
                v = *reinterpret_cast<const float4*>(srcp + (size_t)rr * D + colBase + k4);
#pragma unroll
            for (int i = 0; i < 4; i++) {
                int k  = k4 + i;
                int sz = ((k >> 3) & 3) << 2;
                float vi = (i == 0) ? v.x : (i == 1) ? v.y : (i == 2) ? v.z : v.w;
                sX[k * XSTRIDE + (r ^ sz)] = vi;
            }
        }
        __syncthreads();

        const float4* wbase = reinterpret_cast<const float4*>(sW) + (kc * 32) * 17 + cg;

#pragma unroll 4
        for (int kk = 0; kk < 32; kk++) {
            int sz = ((kk >> 3) & 3) << 2;
            float2 xv = *reinterpret_cast<const float2*>(sX + kk * XSTRIDE + ((rg * 2) ^ sz));
            float4 wa = wbase[kk * 17];
            float4 wb = wbase[kk * 17 + 8];
            float w8[8] = {wa.x, wa.y, wa.z, wa.w, wb.x, wb.y, wb.z, wb.w};
#pragma unroll
            for (int j = 0; j < 8; j++) {
                acc[0][j] = fmaf(xv.x, w8[j], acc[0][j]);
                acc[1][j] = fmaf(xv.y, w8[j], acc[1][j]);
            }
        }
    }

    float bj[8];
#pragma unroll
    for (int j = 0; j < 8; j++) bj[j] = sB[cg * 8 + j];

#pragma unroll
    for (int i = 0; i < 2; i++) {
        int rr = rowBase + rg * 2 + i;
        if (rr < N_NODES) {
            float4 o0, o1;
            o0.x = fmaxf(acc[i][0] + bj[0], 0.f);
            o0.y = fmaxf(acc[i][1] + bj[1], 0.f);
            o0.z = fmaxf(acc[i][2] + bj[2], 0.f);
            o0.w = fmaxf(acc[i][3] + bj[3], 0.f);
            o1.x = fmaxf(acc[i][4] + bj[4], 0.f);
            o1.y = fmaxf(acc[i][5] + bj[5], 0.f);
            o1.z = fmaxf(acc[i][6] + bj[6], 0.f);
            o1.w = fmaxf(acc[i][7] + bj[7], 0.f);
            float4* op = reinterpret_cast<float4*>(out + (size_t)rr * D + cg * 8);
            op[0] = o0;
            op[1] = o1;
        }
    }
}

// ---------------------------------------------------------------------------
// kernel_launch
//   0: h [N,D] f32   1: edge_src [E] i32   2: edge_dst [E] i32   3: edge_w [E] f32
//   4: W_self [D,D]  5: b_self [D]         6: W_neigh [D,D]      7: b_neigh [D]
// ---------------------------------------------------------------------------
extern "C" void kernel_launch(void* const* d_in, const int* in_sizes, int n_in,
                              void* d_out, int out_size) {
    const float* h        = (const float*)d_in[0];
    const int*   edge_src = (const int*)  d_in[1];
    const int*   edge_dst = (const int*)  d_in[2];
    const float* edge_w   = (const float*)d_in[3];
    const float* W_self   = (const float*)d_in[4];
    const float* b_self   = (const float*)d_in[5];
    const float* W_neigh  = (const float*)d_in[6];
    const float* b_neigh  = (const float*)d_in[7];
    float* out = (float*)d_out;

    reset_kernel<<<1, 32>>>();

    {
        // 8 edges per thread (R7 configuration)
        int threadsTotal = N_EDGES / 8;
        int blocks = (threadsTotal + 255) / 256;
        bucket_kernel<<<blocks, 256>>>((const int4*)edge_src, (const int4*)edge_dst,
                                       (const float4*)edge_w);
    }

    // launch-slot shim: puts gather in the ncu capture slot (also harmless
    // re-zero of the overflow counter, whose bucket-phase value is only
    // consumed when a node exceeds CAP — never for this input)
    reset_kernel<<<1, 32>>>();

    {
        int blocks = (N_NODES + GW - 1) / GW;
        gather_kernel<<<blocks, GW * 32>>>(h);
    }

    {
        int blocks = (N_NODES + ROWS - 1) / ROWS;
        dense_kernel<<<blocks, DBLOCK>>>(h, W_self, b_self, W_neigh, b_neigh, out);
    }
}

// round 16
// speedup vs baseline: 2.3082x; 1.4824x over previous
#include <cuda_runtime.h>
#include <cuda_bf16.h>
#include <mma.h>
#include <cstdint>

using namespace nvcuda;

#define N_NODES 50000
#define N_EDGES 800000
#define D       64
#define CAP     64         // bucket capacity per node (max degree ~35 for this input)
#define OVF_MAX 4096

#define DTHREADS 256       // dense: 8 warps, warp w owns rows [16w,16w+16)
#define LDA      72        // bf16 row stride (mult of 8; 144B -> conflict-free ldmatrix)

// smem byte offsets for dense_tc (dynamic)
#define SM_AH    0                         // 128 x 72 bf16 = 18432
#define SM_AL    18432                     // 128 x 72 bf16
#define SM_BH    36864                     // 64 x 72 bf16 = 9216
#define SM_BL    46080                     // 64 x 72 bf16
#define SM_BIAS  55296                     // 64 f32 = 256
#define SM_TOTAL 55552
// output staging reuses [SM_AH, SM_AH+32768) as float[128][64]

// Scratch (__device__ globals; zero-initialized at module load).
// Invariants restored every call: g_cnt zeroed by gather, g_ovf_cnt by reset.
__device__ int  g_cnt[N_NODES];
__device__ int2 g_edge[N_NODES * CAP];   // bucket slots: {src, float_as_int(w)}
__device__ int  g_ovf_cnt;
__device__ int4 g_ovf[OVF_MAX];          // {dst, src, w_bits, pad} overflow spill
__device__ float g_neigh[N_NODES * D];

// ---------------------------------------------------------------------------
// K0: tiny reset (keeps dense in the ncu capture slot)
// ---------------------------------------------------------------------------
__global__ void reset_kernel() {
    if (threadIdx.x == 0 && blockIdx.x == 0) g_ovf_cnt = 0;
}

// ---------------------------------------------------------------------------
// K1: bucket-scatter edges (R7 configuration: 8 edges/thread, interleaved).
// ---------------------------------------------------------------------------
__device__ __forceinline__ void bucket_put(int d, int s, float w) {
    int p = atomicAdd(&g_cnt[d], 1);
    if (p < CAP) {
        g_edge[d * CAP + p] = make_int2(s, __float_as_int(w));
    } else {
        int o = atomicAdd(&g_ovf_cnt, 1);
        if (o < OVF_MAX) g_ovf[o] = make_int4(d, s, __float_as_int(w), 0);
    }
}

__global__ void bucket_kernel(const int4*   __restrict__ src4,
                              const int4*   __restrict__ dst4,
                              const float4* __restrict__ w4) {
    int t = blockIdx.x * blockDim.x + threadIdx.x;
    int base = t * 2;
    const int NQ = N_EDGES / 4;
#pragma unroll
    for (int g = 0; g < 2; g++) {
        int q = base + g;
        if (q < NQ) {
            int4   s = src4[q];
            int4   d = dst4[q];
            float4 w = w4[q];
            bucket_put(d.x, s.x, w.x);
            bucket_put(d.y, s.y, w.y);
            bucket_put(d.z, s.z, w.z);
            bucket_put(d.w, s.w, w.w);
        }
    }
}

// ---------------------------------------------------------------------------
// K2: gather v2 (unchanged from R14) — 2 edges per warp-load via LDG.128.
// ---------------------------------------------------------------------------
#define GW 8
__global__ __launch_bounds__(GW * 32)
void gather_kernel(const float* __restrict__ h) {
    __shared__ int2 sE[GW][32];
    int wslot = threadIdx.x >> 5;
    int warp  = (blockIdx.x * blockDim.x + threadIdx.x) >> 5;
    int lane  = threadIdx.x & 31;
    if (warp >= N_NODES) return;

    int cnt = g_cnt[warp];
    int m   = min(cnt, CAP);
    const int2* bucket = g_edge + warp * CAP;

    const int half = lane >> 4;
    const int hl   = lane & 15;

    float4 acc = make_float4(0.f, 0.f, 0.f, 0.f);
    const float* hq = h + 4 * hl;

    for (int e0 = 0; e0 < m; e0 += 32) {
        int n = min(32, m - e0);
        if (lane < n) sE[wslot][lane] = bucket[e0 + lane];
        __syncwarp();

        int j = 0;
        for (; j + 8 <= n; j += 8) {
            float4 hv[4];
            float  ww[4];
#pragma unroll
            for (int q = 0; q < 4; q++) {
                int2 e = sE[wslot][j + 2 * q + half];
                ww[q] = __int_as_float(e.y);
                hv[q] = *reinterpret_cast<const float4*>(hq + (size_t)e.x * D);
            }
#pragma unroll
            for (int q = 0; q < 4; q++) {
                acc.x = fmaf(ww[q], hv[q].x, acc.x);
                acc.y = fmaf(ww[q], hv[q].y, acc.y);
                acc.z = fmaf(ww[q], hv[q].z, acc.z);
                acc.w = fmaf(ww[q], hv[q].w, acc.w);
            }
        }
        for (; j < n; j += 2) {
            int idx = j + half;
            if (idx < n) {
                int2 e = sE[wslot][idx];
                float wv = __int_as_float(e.y);
                float4 hv = *reinterpret_cast<const float4*>(hq + (size_t)e.x * D);
                acc.x = fmaf(wv, hv.x, acc.x);
                acc.y = fmaf(wv, hv.y, acc.y);
                acc.z = fmaf(wv, hv.z, acc.z);
                acc.w = fmaf(wv, hv.w, acc.w);
            }
        }
        __syncwarp();
    }

    if (cnt > CAP && half == 0) {
        int oc = min(g_ovf_cnt, OVF_MAX);
        for (int i = 0; i < oc; i++) {
            int4 e = g_ovf[i];
            if (e.x == warp) {
                float wv = __int_as_float(e.z);
                float4 hv = *reinterpret_cast<const float4*>(hq + (size_t)e.y * D);
                acc.x = fmaf(wv, hv.x, acc.x);
                acc.y = fmaf(wv, hv.y, acc.y);
                acc.z = fmaf(wv, hv.z, acc.z);
                acc.w = fmaf(wv, hv.w, acc.w);
            }
        }
    }

    acc.x += __shfl_xor_sync(0xffffffffu, acc.x, 16);
    acc.y += __shfl_xor_sync(0xffffffffu, acc.y, 16);
    acc.z += __shfl_xor_sync(0xffffffffu, acc.z, 16);
    acc.w += __shfl_xor_sync(0xffffffffu, acc.w, 16);

    if (half == 0)
        *reinterpret_cast<float4*>(g_neigh + (size_t)warp * D + 4 * hl) = acc;
    if (lane == 0) g_cnt[warp] = 0;
}

// ---------------------------------------------------------------------------
// K3: dense via wmma bf16 split (3-pass): out = relu(h@Ws^T + neigh@Wn^T + b)
// 391 CTAs x 256 thr; warp w owns rows [16w,16w+16) x 64 cols (4 acc frags).
// Per part (K=64): stage A(128x64)->hi/lo bf16 + W(64x64)->hi/lo bf16 in
// smem (stride 72, ldmatrix conflict-free), then 4 k-steps of
// acc += ah*bh + ah*bl + al*bh  (m16n16k16, fp32 acc).
// Error budget: dropped al*bl term ~2^-16 relative -> rel_err ~1e-5 << 1e-3.
// ---------------------------------------------------------------------------
__global__ __launch_bounds__(DTHREADS)
void dense_tc_kernel(const float* __restrict__ h,
                     const float* __restrict__ Ws, const float* __restrict__ bs,
                     const float* __restrict__ Wn, const float* __restrict__ bn,
                     float* __restrict__ out) {
    extern __shared__ __align__(16) char smem[];
    __nv_bfloat16* aH = reinterpret_cast<__nv_bfloat16*>(smem + SM_AH);
    __nv_bfloat16* aL = reinterpret_cast<__nv_bfloat16*>(smem + SM_AL);
    __nv_bfloat16* bH = reinterpret_cast<__nv_bfloat16*>(smem + SM_BH);
    __nv_bfloat16* bL = reinterpret_cast<__nv_bfloat16*>(smem + SM_BL);
    float*         sB = reinterpret_cast<float*>(smem + SM_BIAS);
    float*         stage = reinterpret_cast<float*>(smem + SM_AH);  // reuse

    const int tid = threadIdx.x;
    const int wid = tid >> 5;
    const int rowBase = blockIdx.x * 128;

    if (tid < 64) sB[tid] = bs[tid] + bn[tid];

    wmma::fragment<wmma::accumulator, 16, 16, 16, float> acc[4];
#pragma unroll
    for (int n = 0; n < 4; n++) wmma::fill_fragment(acc[n], 0.f);

#pragma unroll
    for (int part = 0; part < 2; part++) {
        const float* xsrc = part ? g_neigh : h;
        const float* wsrc = part ? Wn : Ws;

        __syncthreads();   // previous part's mma reads complete

        // Stage A: 128 rows x 64 k -> hi/lo bf16 (coalesced float4 reads)
#pragma unroll
        for (int p = 0; p < 8; p++) {
            int f  = tid + DTHREADS * p;     // 0..2047
            int r  = f >> 4;                 // row 0..127
            int k0 = (f & 15) * 4;
            int rr = rowBase + r;
            float4 v = make_float4(0.f, 0.f, 0.f, 0.f);
            if (rr < N_NODES)
                v = *reinterpret_cast<const float4*>(xsrc + (size_t)rr * D + k0);
            float vv[4] = {v.x, v.y, v.z, v.w};
#pragma unroll
            for (int i = 0; i < 4; i++) {
                __nv_bfloat16 hi = __float2bfloat16(vv[i]);
                __nv_bfloat16 lo = __float2bfloat16(vv[i] - __bfloat162float(hi));
                aH[r * LDA + k0 + i] = hi;
                aL[r * LDA + k0 + i] = lo;
            }
        }

        // Stage B: W [j=64][k=64] -> hi/lo bf16 rows (col-major B: (k,n)=b[n*LDA+k])
#pragma unroll
        for (int p = 0; p < 4; p++) {
            int f  = tid + DTHREADS * p;     // 0..1023
            int j  = f >> 4;
            int k0 = (f & 15) * 4;
            float4 v = *reinterpret_cast<const float4*>(wsrc + j * 64 + k0);
            float vv[4] = {v.x, v.y, v.z, v.w};
#pragma unroll
            for (int i = 0; i < 4; i++) {
                __nv_bfloat16 hi = __float2bfloat16(vv[i]);
                __nv_bfloat16 lo = __float2bfloat16(vv[i] - __bfloat162float(hi));
                bH[j * LDA + k0 + i] = hi;
                bL[j * LDA + k0 + i] = lo;
            }
        }
        __syncthreads();

        const __nv_bfloat16* arow = aH + wid * 16 * LDA;
        const __nv_bfloat16* arol = aL + wid * 16 * LDA;

#pragma unroll
        for (int ks = 0; ks < 4; ks++) {
            wmma::fragment<wmma::matrix_a, 16, 16, 16, __nv_bfloat16, wmma::row_major> ah, al;
            wmma::load_matrix_sync(ah, arow + ks * 16, LDA);
            wmma::load_matrix_sync(al, arol + ks * 16, LDA);
#pragma unroll
            for (int n = 0; n < 4; n++) {
                wmma::fragment<wmma::matrix_b, 16, 16, 16, __nv_bfloat16, wmma::col_major> bh, bl;
                wmma::load_matrix_sync(bh, bH + n * 16 * LDA + ks * 16, LDA);
                wmma::load_matrix_sync(bl, bL + n * 16 * LDA + ks * 16, LDA);
                wmma::mma_sync(acc[n], ah, bh, acc[n]);
                wmma::mma_sync(acc[n], ah, bl, acc[n]);
                wmma::mma_sync(acc[n], al, bh, acc[n]);
            }
        }
    }

    // Epilogue: stage fp32 result (reuses A smem), bias + relu, coalesced out
    __syncthreads();
#pragma unroll
    for (int n = 0; n < 4; n++)
        wmma::store_matrix_sync(stage + wid * 16 * 64 + n * 16, acc[n], 64,
                                wmma::mem_row_major);
    __syncthreads();

#pragma unroll
    for (int p = 0; p < 8; p++) {
        int f  = tid + DTHREADS * p;         // 0..2047
        int r  = f >> 4;                     // row 0..127
        int c4 = (f & 15) * 4;
        int rr = rowBase + r;
        if (rr < N_NODES) {
            float4 v = *reinterpret_cast<const float4*>(stage + r * 64 + c4);
            float4 o;
            o.x = fmaxf(v.x + sB[c4 + 0], 0.f);
            o.y = fmaxf(v.y + sB[c4 + 1], 0.f);
            o.z = fmaxf(v.z + sB[c4 + 2], 0.f);
            o.w = fmaxf(v.w + sB[c4 + 3], 0.f);
            *reinterpret_cast<float4*>(out + (size_t)rr * D + c4) = o;
        }
    }
}

// ---------------------------------------------------------------------------
// kernel_launch
//   0: h [N,D] f32   1: edge_src [E] i32   2: edge_dst [E] i32   3: edge_w [E] f32
//   4: W_self [D,D]  5: b_self [D]         6: W_neigh [D,D]      7: b_neigh [D]
// ---------------------------------------------------------------------------
extern "C" void kernel_launch(void* const* d_in, const int* in_sizes, int n_in,
                              void* d_out, int out_size) {
    const float* h        = (const float*)d_in[0];
    const int*   edge_src = (const int*)  d_in[1];
    const int*   edge_dst = (const int*)  d_in[2];
    const float* edge_w   = (const float*)d_in[3];
    const float* W_self   = (const float*)d_in[4];
    const float* b_self   = (const float*)d_in[5];
    const float* W_neigh  = (const float*)d_in[6];
    const float* b_neigh  = (const float*)d_in[7];
    float* out = (float*)d_out;

    reset_kernel<<<1, 32>>>();

    {
        int threadsTotal = N_EDGES / 8;
        int blocks = (threadsTotal + 255) / 256;
        bucket_kernel<<<blocks, 256>>>((const int4*)edge_src, (const int4*)edge_dst,
                                       (const float4*)edge_w);
    }

    {
        int blocks = (N_NODES + GW - 1) / GW;
        gather_kernel<<<blocks, GW * 32>>>(h);
    }

    {
        static bool attrSet = false;
        if (!attrSet) {
            cudaFuncSetAttribute(dense_tc_kernel,
                                 cudaFuncAttributeMaxDynamicSharedMemorySize, SM_TOTAL);
            attrSet = true;
        }
        int blocks = (N_NODES + 127) / 128;
        dense_tc_kernel<<<blocks, DTHREADS, SM_TOTAL>>>(h, W_self, b_self,
                                                        W_neigh, b_neigh, out);
    }
}